// round 1
// baseline (speedup 1.0000x reference)
#include <cuda_runtime.h>

// ---------------------------------------------------------------------------
// TeamMovementModel: two LSTMs (H=128, T=128) + FC.
//   player LSTM: 1408 sequences (64 batch x 22 players), input dim 2
//   ball   LSTM:   64 sequences, input dim 2
//   out[b,p,:40] = [player_h(b,p), ball_h(b)] @ fc_w.T + fc_b
//
// Design: one wave of 148 CTAs (256 threads each), each CTA owns 10 sequences
// and runs the full 128-step recurrence. Recurrent weights W^T live in SMEM
// (k=0..87) + per-thread registers (k=88..127). Inner product uses packed
// fp32x2 FFMA2 (2 sequences per instruction) for 128 FMA/cyc/SM.
// ---------------------------------------------------------------------------

#define Hh       128
#define GATES    512          // 4*H
#define Tt       128
#define Mseq     10           // sequences per CTA
#define MP       12           // padded row stride (floats) for smem tiles
#define KSM      88           // k-rows of W^T kept in smem
#define KRG      40           // k-rows of W^T kept in registers
#define NPLAYER  1408
#define NBALL    64
#define PCTAS    141          // ceil(1408/10)
#define NCTAS    148          // 141 player + 7 ball
#define THREADS  256

// smem layout (floats):
//   Wt  [KSM][512]   : 45056
//   g_s [512][MP]    :  6144
//   h_s [128][MP]    :  1536
//   x_s [10][256]    :  2560
#define SM_WT   0
#define SM_G    (KSM * GATES)                 // 45056
#define SM_H    (SM_G + GATES * MP)           // 51200
#define SM_X    (SM_H + Hh * MP)              // 52736
#define SM_FLOATS (SM_X + Mseq * 256)         // 55296
#define SM_BYTES  (SM_FLOATS * 4)             // 221184

__device__ float g_hid[(NPLAYER + NBALL) * Hh];   // final hidden states

// ---- fp32x2 helpers ----
__device__ __forceinline__ unsigned long long splat2(float x) {
    unsigned long long r; unsigned int u = __float_as_uint(x);
    asm("mov.b64 %0, {%1, %1};" : "=l"(r) : "r"(u));
    return r;
}
__device__ __forceinline__ unsigned long long pack2(float lo, float hi) {
    unsigned long long r;
    asm("mov.b64 %0, {%1, %2};" : "=l"(r)
        : "r"(__float_as_uint(lo)), "r"(__float_as_uint(hi)));
    return r;
}
__device__ __forceinline__ void ffma2(unsigned long long& d,
                                      unsigned long long a,
                                      unsigned long long b) {
    asm("fma.rn.f32x2 %0, %1, %2, %0;" : "+l"(d) : "l"(a), "l"(b));
}

__device__ __forceinline__ float sigf(float x) {
    return __fdividef(1.0f, 1.0f + __expf(-x));
}
__device__ __forceinline__ float tanh_acc(float x) {
    return __fdividef(2.0f, 1.0f + __expf(-2.0f * x)) - 1.0f;
}

__global__ __launch_bounds__(THREADS, 1)
void lstm_kernel(const float* __restrict__ xp, const float* __restrict__ xb,
                 const float* __restrict__ p_wih, const float* __restrict__ p_whh,
                 const float* __restrict__ p_bih, const float* __restrict__ p_bhh,
                 const float* __restrict__ b_wih, const float* __restrict__ b_whh,
                 const float* __restrict__ b_bih, const float* __restrict__ b_bhh)
{
    extern __shared__ float sm[];
    float* Wt  = sm + SM_WT;   // [KSM][512], Wt[k*512+j] = whh[j][k]
    float* g_s = sm + SM_G;    // [512][MP]
    float* h_s = sm + SM_H;    // [128][MP]
    float* x_s = sm + SM_X;    // [10][256]  (t,d packed)

    const int tid = threadIdx.x;
    const int cta = blockIdx.x;
    const bool is_ball = (cta >= PCTAS);

    const float* wih  = is_ball ? b_wih : p_wih;
    const float* whh  = is_ball ? b_whh : p_whh;
    const float* bih  = is_ball ? b_bih : p_bih;
    const float* bhh  = is_ball ? b_bhh : p_bhh;
    const float* xbase = is_ball ? xb : xp;
    const int seq0  = is_ball ? (cta - PCTAS) * Mseq : cta * Mseq;
    const int ntot  = is_ball ? NBALL : NPLAYER;
    const int Mact  = min(Mseq, ntot - seq0);
    const int gbase = is_ball ? NPLAYER : 0;

    // --- fill Wt smem (transposed): coalesced LDG over k ---
    for (int idx = tid; idx < GATES * KSM; idx += THREADS) {
        int j = idx / KSM;
        int k = idx - j * KSM;
        Wt[k * GATES + j] = whh[j * Hh + k];
    }
    // --- zero h state ---
    for (int idx = tid; idx < Hh * MP; idx += THREADS) h_s[idx] = 0.0f;
    // --- load x tile (zero-pad missing sequences) ---
    for (int m = 0; m < Mseq; m++) {
        x_s[m * 256 + tid] = (m < Mact) ? xbase[(seq0 + m) * 256 + tid] : 0.0f;
    }

    // --- per-thread constants: 2 gate columns j0, j1 ---
    const int j0 = 2 * tid, j1 = 2 * tid + 1;
    const float bias0 = bih[j0] + bhh[j0];
    const float bias1 = bih[j1] + bhh[j1];
    const float wi00 = wih[j0 * 2 + 0], wi01 = wih[j0 * 2 + 1];
    const float wi10 = wih[j1 * 2 + 0], wi11 = wih[j1 * 2 + 1];

    // register-resident weight tail (k = 88..127)
    float wr0[KRG], wr1[KRG];
    #pragma unroll
    for (int kk = 0; kk < KRG; kk++) {
        wr0[kk] = whh[j0 * Hh + KSM + kk];
        wr1[kk] = whh[j1 * Hh + KSM + kk];
    }

    float c[5] = {0.f, 0.f, 0.f, 0.f, 0.f};   // cell state for (u,m) pairs

    __syncthreads();

    for (int step = 0; step < Tt; step++) {
        // ---- gate pre-activations: init with bias + input projection ----
        unsigned long long acc0[5], acc1[5];
        #pragma unroll
        for (int q = 0; q < 5; q++) {
            const float xa0 = x_s[(2 * q)     * 256 + step * 2];
            const float xa1 = x_s[(2 * q)     * 256 + step * 2 + 1];
            const float xb0 = x_s[(2 * q + 1) * 256 + step * 2];
            const float xb1 = x_s[(2 * q + 1) * 256 + step * 2 + 1];
            acc0[q] = pack2(bias0 + wi00 * xa0 + wi01 * xa1,
                            bias0 + wi00 * xb0 + wi01 * xb1);
            acc1[q] = pack2(bias1 + wi10 * xa0 + wi11 * xa1,
                            bias1 + wi10 * xb0 + wi11 * xb1);
        }

        // ---- recurrent GEMM: smem-weight part ----
        #pragma unroll 8
        for (int k = 0; k < KSM; k++) {
            const unsigned long long* hq =
                (const unsigned long long*)(h_s + k * MP);
            unsigned long long h01 = hq[0], h23 = hq[1], h45 = hq[2],
                               h67 = hq[3], h89 = hq[4];
            float2 w = *(const float2*)(Wt + k * GATES + j0);
            unsigned long long w0 = splat2(w.x), w1 = splat2(w.y);
            ffma2(acc0[0], h01, w0); ffma2(acc1[0], h01, w1);
            ffma2(acc0[1], h23, w0); ffma2(acc1[1], h23, w1);
            ffma2(acc0[2], h45, w0); ffma2(acc1[2], h45, w1);
            ffma2(acc0[3], h67, w0); ffma2(acc1[3], h67, w1);
            ffma2(acc0[4], h89, w0); ffma2(acc1[4], h89, w1);
        }
        // ---- recurrent GEMM: register-weight tail ----
        #pragma unroll
        for (int kk = 0; kk < KRG; kk++) {
            const int k = KSM + kk;
            const unsigned long long* hq =
                (const unsigned long long*)(h_s + k * MP);
            unsigned long long h01 = hq[0], h23 = hq[1], h45 = hq[2],
                               h67 = hq[3], h89 = hq[4];
            unsigned long long w0 = splat2(wr0[kk]), w1 = splat2(wr1[kk]);
            ffma2(acc0[0], h01, w0); ffma2(acc1[0], h01, w1);
            ffma2(acc0[1], h23, w0); ffma2(acc1[1], h23, w1);
            ffma2(acc0[2], h45, w0); ffma2(acc1[2], h45, w1);
            ffma2(acc0[3], h67, w0); ffma2(acc1[3], h67, w1);
            ffma2(acc0[4], h89, w0); ffma2(acc1[4], h89, w1);
        }

        // ---- scatter gates to smem ----
        #pragma unroll
        for (int q = 0; q < 5; q++) {
            *(unsigned long long*)(g_s + j0 * MP + 2 * q) = acc0[q];
            *(unsigned long long*)(g_s + j1 * MP + 2 * q) = acc1[q];
        }
        __syncthreads();

        // ---- elementwise LSTM cell update: thread owns 5 (u,m) pairs ----
        #pragma unroll
        for (int q = 0; q < 5; q++) {
            const int e = q * THREADS + tid;       // 0..1279
            const int u = e / Mseq;
            const int m = e - u * Mseq;
            const float gi = g_s[u            * MP + m];
            const float gf = g_s[(u +     Hh) * MP + m];
            const float gg = g_s[(u + 2 * Hh) * MP + m];
            const float go = g_s[(u + 3 * Hh) * MP + m];
            const float fi = sigf(gi);
            const float ff = sigf(gf);
            const float fg = tanh_acc(gg);
            const float fo = sigf(go);
            c[q] = ff * c[q] + fi * fg;
            h_s[u * MP + m] = fo * tanh_acc(c[q]);
        }
        __syncthreads();
    }

    // ---- write final hidden states ----
    #pragma unroll
    for (int q = 0; q < 5; q++) {
        const int e = q * THREADS + tid;
        const int u = e / Mseq;
        const int m = e - u * Mseq;
        if (m < Mact)
            g_hid[(gbase + seq0 + m) * Hh + u] = h_s[u * MP + m];
    }
}

__global__ void fc_kernel(const float* __restrict__ fc_w,
                          const float* __restrict__ fc_b,
                          float* __restrict__ out)
{
    __shared__ float hs[2 * Hh];
    const int s = blockIdx.x;          // 0..1407 = b*22+p
    const int b = s / 22;
    const int t = threadIdx.x;         // 64 threads

    for (int i = t; i < Hh; i += 64) {
        hs[i]      = g_hid[s * Hh + i];
        hs[Hh + i] = g_hid[(NPLAYER + b) * Hh + i];
    }
    __syncthreads();

    if (t < 40) {
        float acc = fc_b[t];
        #pragma unroll 8
        for (int k = 0; k < 2 * Hh; k++)
            acc += hs[k] * fc_w[t * 2 * Hh + k];
        out[s * 40 + t] = acc;
    }
}

extern "C" void kernel_launch(void* const* d_in, const int* in_sizes, int n_in,
                              void* d_out, int out_size)
{
    const float* xp    = (const float*)d_in[0];
    const float* xb    = (const float*)d_in[1];
    const float* p_wih = (const float*)d_in[2];
    const float* p_whh = (const float*)d_in[3];
    const float* p_bih = (const float*)d_in[4];
    const float* p_bhh = (const float*)d_in[5];
    const float* b_wih = (const float*)d_in[6];
    const float* b_whh = (const float*)d_in[7];
    const float* b_bih = (const float*)d_in[8];
    const float* b_bhh = (const float*)d_in[9];
    const float* fc_w  = (const float*)d_in[10];
    const float* fc_b  = (const float*)d_in[11];
    float* out = (float*)d_out;

    cudaFuncSetAttribute(lstm_kernel,
                         cudaFuncAttributeMaxDynamicSharedMemorySize, SM_BYTES);

    lstm_kernel<<<NCTAS, THREADS, SM_BYTES>>>(xp, xb,
                                              p_wih, p_whh, p_bih, p_bhh,
                                              b_wih, b_whh, b_bih, b_bhh);
    fc_kernel<<<NPLAYER, 64>>>(fc_w, fc_b, out);
}

// round 2
// speedup vs baseline: 1.1135x; 1.1135x over previous
#include <cuda_runtime.h>

// ---------------------------------------------------------------------------
// TeamMovementModel: two LSTMs (H=128, T=128) + FC.
// R2: paired-k GEMM (LDS.128, halves LSU pressure), producer-side
// activations, conflict-free gate exchange layout, smem-cached FC.
// ---------------------------------------------------------------------------

#define Hh       128
#define GATES    512
#define Tt       128
#define Mseq     10
#define KSM      94           // k-rows of W^T in smem (even)
#define KRG      34           // k-rows of W^T in registers (even)
#define NPLAYER  1408
#define NBALL    64
#define PCTAS    141
#define NCTAS    148
#define THREADS  256
#define GPS      22           // gate-pair stride: [j/2][parity][10] padded to 22

// smem (floats): Wt2 [KSM/2][512][2] | g_s [256][22] | h_s [128][10] | x_s [256][10]
#define SM_WT   0
#define SM_G    (KSM * GATES)                     // 48128
#define SM_H    (SM_G + 256 * GPS)                // 53760
#define SM_X    (SM_H + Hh * Mseq)                // 55040
#define SM_FLOATS (SM_X + 256 * Mseq)             // 57600
#define SM_BYTES  (SM_FLOATS * 4)                 // 230400

__device__ float g_hid[(NPLAYER + NBALL) * Hh];

typedef unsigned long long u64;

__device__ __forceinline__ u64 splat2(float x) {
    u64 r; unsigned int u = __float_as_uint(x);
    asm("mov.b64 %0, {%1, %1};" : "=l"(r) : "r"(u));
    return r;
}
__device__ __forceinline__ u64 pack2(float lo, float hi) {
    u64 r;
    asm("mov.b64 %0, {%1, %2};" : "=l"(r)
        : "r"(__float_as_uint(lo)), "r"(__float_as_uint(hi)));
    return r;
}
__device__ __forceinline__ void unpack2(u64 v, float& lo, float& hi) {
    unsigned int a, b;
    asm("mov.b64 {%0, %1}, %2;" : "=r"(a), "=r"(b) : "l"(v));
    lo = __uint_as_float(a); hi = __uint_as_float(b);
}
__device__ __forceinline__ void ffma2(u64& d, u64 a, u64 b) {
    asm("fma.rn.f32x2 %0, %1, %2, %0;" : "+l"(d) : "l"(a), "l"(b));
}

__device__ __forceinline__ float sigf(float x) {
    return __fdividef(1.0f, 1.0f + __expf(-x));
}
__device__ __forceinline__ float tanh_acc(float x) {
    return __fdividef(2.0f, 1.0f + __expf(-2.0f * x)) - 1.0f;
}

// One k-pair (k=2*k2, 2*k2+1) of the recurrent GEMM for both gate columns.
#define MMA_PAIR(HPTR, W00, W01, W10, W11) do {                                \
    const ulonglong2* hv = (const ulonglong2*)(HPTR);                          \
    ulonglong2 A = hv[0], B = hv[1], C = hv[2], D = hv[3], E = hv[4];          \
    u64 s00 = splat2(W00), s01 = splat2(W01);                                  \
    u64 s10 = splat2(W10), s11 = splat2(W11);                                  \
    ffma2(acc0[0], A.x, s00); ffma2(acc1[0], A.x, s10);                        \
    ffma2(acc0[1], A.y, s00); ffma2(acc1[1], A.y, s10);                        \
    ffma2(acc0[2], B.x, s00); ffma2(acc1[2], B.x, s10);                        \
    ffma2(acc0[3], B.y, s00); ffma2(acc1[3], B.y, s10);                        \
    ffma2(acc0[4], C.x, s00); ffma2(acc1[4], C.x, s10);                        \
    ffma2(acc0[0], C.y, s01); ffma2(acc1[0], C.y, s11);                        \
    ffma2(acc0[1], D.x, s01); ffma2(acc1[1], D.x, s11);                        \
    ffma2(acc0[2], D.y, s01); ffma2(acc1[2], D.y, s11);                        \
    ffma2(acc0[3], E.x, s01); ffma2(acc1[3], E.x, s11);                        \
    ffma2(acc0[4], E.y, s01); ffma2(acc1[4], E.y, s11);                        \
} while (0)

__global__ __launch_bounds__(THREADS, 1)
void lstm_kernel(const float* __restrict__ xp, const float* __restrict__ xb,
                 const float* __restrict__ p_wih, const float* __restrict__ p_whh,
                 const float* __restrict__ p_bih, const float* __restrict__ p_bhh,
                 const float* __restrict__ b_wih, const float* __restrict__ b_whh,
                 const float* __restrict__ b_bih, const float* __restrict__ b_bhh)
{
    extern __shared__ float sm[];
    float* Wt  = sm + SM_WT;   // [k2][j][parity] : ((k2*512)+j)*2 + (k&1)
    float* g_s = sm + SM_G;    // [j>>1][j&1][m], pair stride 22
    float* h_s = sm + SM_H;    // [k][m] stride 10 (packed)
    float* x_s = sm + SM_X;    // [(t*2+d)][m] stride 10

    const int tid = threadIdx.x;
    const int cta = blockIdx.x;
    const bool is_ball = (cta >= PCTAS);

    const float* wih   = is_ball ? b_wih : p_wih;
    const float* whh   = is_ball ? b_whh : p_whh;
    const float* bih   = is_ball ? b_bih : p_bih;
    const float* bhh   = is_ball ? b_bhh : p_bhh;
    const float* xbase = is_ball ? xb : xp;
    const int seq0  = is_ball ? (cta - PCTAS) * Mseq : cta * Mseq;
    const int ntot  = is_ball ? NBALL : NPLAYER;
    const int Mact  = min(Mseq, ntot - seq0);
    const int gbase = is_ball ? NPLAYER : 0;

    // --- Wt smem fill: pair-interleaved transpose ---
    for (int idx = tid; idx < GATES * KSM; idx += THREADS) {
        int j  = idx / KSM;
        int kk = idx - j * KSM;
        Wt[((kk >> 1) * GATES + j) * 2 + (kk & 1)] = whh[j * Hh + kk];
    }
    // --- zero h ---
    for (int idx = tid; idx < Hh * Mseq; idx += THREADS) h_s[idx] = 0.0f;
    // --- x tile, transposed to [(t,d)][m] ---
    for (int m = 0; m < Mseq; m++) {
        x_s[tid * Mseq + m] = (m < Mact) ? xbase[(seq0 + m) * 256 + tid] : 0.0f;
    }

    // --- per-thread constants: gate columns j0 = 2*tid, j1 = 2*tid+1 ---
    const int j0 = 2 * tid, j1 = 2 * tid + 1;
    const u64 bias0p = splat2(bih[j0] + bhh[j0]);
    const u64 bias1p = splat2(bih[j1] + bhh[j1]);
    const u64 wi00p = splat2(wih[j0 * 2 + 0]), wi01p = splat2(wih[j0 * 2 + 1]);
    const u64 wi10p = splat2(wih[j1 * 2 + 0]), wi11p = splat2(wih[j1 * 2 + 1]);
    const bool is_tanh_gate = (tid >= 128) && (tid < 192);   // g-gate columns

    // register tail of W^T (k = KSM..127)
    float wr0[KRG], wr1[KRG];
    #pragma unroll
    for (int kk = 0; kk < KRG; kk++) {
        wr0[kk] = whh[j0 * Hh + KSM + kk];
        wr1[kk] = whh[j1 * Hh + KSM + kk];
    }

    float c[5] = {0.f, 0.f, 0.f, 0.f, 0.f};

    __syncthreads();

    for (int step = 0; step < Tt; step++) {
        // ---- init accumulators: bias + input projection ----
        u64 acc0[5], acc1[5];
        const float* xr0 = x_s + (2 * step) * Mseq;       // d=0 row
        const float* xr1 = x_s + (2 * step + 1) * Mseq;   // d=1 row
        #pragma unroll
        for (int q = 0; q < 5; q++) {
            u64 X0 = *(const u64*)(xr0 + 2 * q);
            u64 X1 = *(const u64*)(xr1 + 2 * q);
            u64 a0 = bias0p, a1 = bias1p;
            ffma2(a0, X0, wi00p); ffma2(a0, X1, wi01p);
            ffma2(a1, X0, wi10p); ffma2(a1, X1, wi11p);
            acc0[q] = a0; acc1[q] = a1;
        }

        // ---- recurrent GEMM: smem-weight pairs ----
        #pragma unroll 4
        for (int k2 = 0; k2 < KSM / 2; k2++) {
            float4 wv = *(const float4*)(Wt + (k2 * GATES) * 2 + 4 * tid);
            MMA_PAIR(h_s + k2 * 2 * Mseq, wv.x, wv.y, wv.z, wv.w);
        }
        // ---- recurrent GEMM: register-weight tail ----
        #pragma unroll
        for (int kk2 = 0; kk2 < KRG / 2; kk2++) {
            MMA_PAIR(h_s + (KSM + 2 * kk2) * Mseq,
                     wr0[2 * kk2], wr0[2 * kk2 + 1],
                     wr1[2 * kk2], wr1[2 * kk2 + 1]);
        }

        // ---- producer-side activations (warp-uniform gate type) + scatter ----
        float* g0 = g_s + tid * GPS;          // j0 slot
        float* g1 = g_s + tid * GPS + Mseq;   // j1 slot
        if (is_tanh_gate) {
            #pragma unroll
            for (int q = 0; q < 5; q++) {
                float a0, a1, b0, b1;
                unpack2(acc0[q], a0, a1); unpack2(acc1[q], b0, b1);
                *(u64*)(g0 + 2 * q) = pack2(tanh_acc(a0), tanh_acc(a1));
                *(u64*)(g1 + 2 * q) = pack2(tanh_acc(b0), tanh_acc(b1));
            }
        } else {
            #pragma unroll
            for (int q = 0; q < 5; q++) {
                float a0, a1, b0, b1;
                unpack2(acc0[q], a0, a1); unpack2(acc1[q], b0, b1);
                *(u64*)(g0 + 2 * q) = pack2(sigf(a0), sigf(a1));
                *(u64*)(g1 + 2 * q) = pack2(sigf(b0), sigf(b1));
            }
        }
        __syncthreads();

        // ---- cell update: c = f*c + i*g ; h = o*tanh(c) ----
        #pragma unroll
        for (int q = 0; q < 5; q++) {
            const int e = q * THREADS + tid;     // 0..1279
            const int u = e / Mseq;
            const int m = e - u * Mseq;
            const int ib = (u >> 1) * GPS + (u & 1) * Mseq + m;
            const float fi = g_s[ib];
            const float ff = g_s[ib + 64 * GPS];
            const float fg = g_s[ib + 128 * GPS];
            const float fo = g_s[ib + 192 * GPS];
            c[q] = ff * c[q] + fi * fg;
            h_s[u * Mseq + m] = fo * tanh_acc(c[q]);
        }
        __syncthreads();
    }

    // ---- write final hidden states ----
    #pragma unroll
    for (int q = 0; q < 5; q++) {
        const int e = q * THREADS + tid;
        const int u = e / Mseq;
        const int m = e - u * Mseq;
        if (m < Mact)
            g_hid[(gbase + seq0 + m) * Hh + u] = h_s[u * Mseq + m];
    }
}

// FC: 128 blocks = (batch b, half of 22 players). fc_w + hidden states in smem.
#define FC_THREADS 448
__global__ __launch_bounds__(FC_THREADS)
void fc_kernel(const float* __restrict__ fc_w,
               const float* __restrict__ fc_b,
               float* __restrict__ out)
{
    __shared__ float fw[40 * 258];     // [40][258] padded
    __shared__ float ph[11 * 128];
    __shared__ float ball[128];

    const int bx   = blockIdx.x;
    const int b    = bx >> 1;
    const int half = bx & 1;
    const int tid  = threadIdx.x;

    for (int idx = tid; idx < 40 * 256; idx += FC_THREADS) {
        int j = idx >> 8, k = idx & 255;
        fw[j * 258 + k] = fc_w[idx];
    }
    for (int idx = tid; idx < 11 * 128; idx += FC_THREADS) {
        int p = idx >> 7, k = idx & 127;
        ph[idx] = g_hid[(b * 22 + half * 11 + p) * Hh + k];
    }
    for (int idx = tid; idx < 128; idx += FC_THREADS)
        ball[idx] = g_hid[(NPLAYER + b) * Hh + idx];
    __syncthreads();

    if (tid < 440) {
        const int p = tid / 40;
        const int j = tid - p * 40;
        const float2* php  = (const float2*)(ph + p * 128);
        const float2* blp  = (const float2*)(ball);
        const float2* fwp0 = (const float2*)(fw + j * 258);
        const float2* fwp1 = (const float2*)(fw + j * 258 + 128);
        float acc = fc_b[j];
        #pragma unroll 8
        for (int k2 = 0; k2 < 64; k2++) {
            float2 hp = php[k2], hb = blp[k2];
            float2 w0 = fwp0[k2], w1 = fwp1[k2];
            acc += hp.x * w0.x + hp.y * w0.y + hb.x * w1.x + hb.y * w1.y;
        }
        out[(b * 22 + half * 11 + p) * 40 + j] = acc;
    }
}

extern "C" void kernel_launch(void* const* d_in, const int* in_sizes, int n_in,
                              void* d_out, int out_size)
{
    const float* xp    = (const float*)d_in[0];
    const float* xb    = (const float*)d_in[1];
    const float* p_wih = (const float*)d_in[2];
    const float* p_whh = (const float*)d_in[3];
    const float* p_bih = (const float*)d_in[4];
    const float* p_bhh = (const float*)d_in[5];
    const float* b_wih = (const float*)d_in[6];
    const float* b_whh = (const float*)d_in[7];
    const float* b_bih = (const float*)d_in[8];
    const float* b_bhh = (const float*)d_in[9];
    const float* fc_w  = (const float*)d_in[10];
    const float* fc_b  = (const float*)d_in[11];
    float* out = (float*)d_out;

    cudaFuncSetAttribute(lstm_kernel,
                         cudaFuncAttributeMaxDynamicSharedMemorySize, SM_BYTES);

    lstm_kernel<<<NCTAS, THREADS, SM_BYTES>>>(xp, xb,
                                              p_wih, p_whh, p_bih, p_bhh,
                                              b_wih, b_whh, b_bih, b_bhh);
    fc_kernel<<<128, FC_THREADS>>>(fc_w, fc_b, out);
}